// round 8
// baseline (speedup 1.0000x reference)
#include <cuda_runtime.h>
#include <math.h>
#include <stdint.h>

// Problem constants: N=50000, E=800000, F1=96, F2=64
#define MAXN 50000
#define MAXE 800000
#define F1 96
#define F2 64
#define SCAN_T 1024

// Scratch (device globals). __align__(16) for float4 access.
__device__ int g_deg[MAXN];          // starts zeroed (BSS); scan re-zeroes it
__device__ int g_off[MAXN + 1];
__device__ int g_cur[MAXN];
__device__ int g_srcs[MAXE];
__device__ __align__(16) float g_m1[MAXN * F1];   // mean of x over neighbors
__device__ __align__(16) float g_h [MAXN * F1];   // layer-1 output
__device__ __align__(16) float g_y2[MAXN * F2];   // h @ w2_r^T

// ---------------------------------------------------------------------------
// tf32 helpers
// ---------------------------------------------------------------------------
__device__ __forceinline__ uint32_t cvt_tf32(float f) {
    uint32_t u;
    asm("cvt.rna.tf32.f32 %0, %1;" : "=r"(u) : "f"(f));
    return u;
}

__device__ __forceinline__ void mma_tf32(float* c,
                                         uint32_t a0, uint32_t a1,
                                         uint32_t a2, uint32_t a3,
                                         uint32_t b0, uint32_t b1) {
    asm volatile(
        "mma.sync.aligned.m16n8k8.row.col.f32.tf32.tf32.f32 "
        "{%0,%1,%2,%3}, {%4,%5,%6,%7}, {%8,%9}, {%0,%1,%2,%3};"
        : "+f"(c[0]), "+f"(c[1]), "+f"(c[2]), "+f"(c[3])
        : "r"(a0), "r"(a1), "r"(a2), "r"(a3), "r"(b0), "r"(b1));
}

__device__ __forceinline__ float elu1(float v) {
    return v > 0.f ? v : (__expf(v) - 1.0f);
}

// ---------------------------------------------------------------------------
// CSR build: histogram -> scan (clears g_deg) -> scatter
// ---------------------------------------------------------------------------
__global__ void hist_kernel(const int* __restrict__ dst, int e) {
    int i4 = (blockIdx.x * blockDim.x + threadIdx.x) * 4;
    if (i4 + 3 < e) {
        int4 d = *(const int4*)(dst + i4);
        atomicAdd(&g_deg[d.x], 1);
        atomicAdd(&g_deg[d.y], 1);
        atomicAdd(&g_deg[d.z], 1);
        atomicAdd(&g_deg[d.w], 1);
    } else {
        for (int i = i4; i < e; i++) atomicAdd(&g_deg[i < e ? dst[i] : 0], i < e ? 1 : 0);
    }
}

__global__ void scan_kernel(int n) {
    __shared__ int ssum[SCAN_T];
    int t = threadIdx.x;
    int chunk = (n + SCAN_T - 1) / SCAN_T;
    int start = t * chunk;
    int end = min(start + chunk, n);
    int local = 0;
    for (int i = start; i < end; i++) local += g_deg[i];
    ssum[t] = local;
    __syncthreads();
    for (int ofs = 1; ofs < SCAN_T; ofs <<= 1) {
        int v = (t >= ofs) ? ssum[t - ofs] : 0;
        __syncthreads();
        ssum[t] += v;
        __syncthreads();
    }
    int run = ssum[t] - local;   // exclusive prefix
    for (int i = start; i < end; i++) {
        int d = g_deg[i];
        g_off[i] = run;
        g_cur[i] = run;
        run += d;
        g_deg[i] = 0;            // leave cleared for the next launch
    }
    if (t == SCAN_T - 1) g_off[n] = ssum[SCAN_T - 1];
}

__global__ void scatter_kernel(const int* __restrict__ src,
                               const int* __restrict__ dst, int e) {
    int i = (blockIdx.x * blockDim.x + threadIdx.x) * 2;
    if (i + 1 < e) {
        int2 s = *(const int2*)(src + i);
        int2 d = *(const int2*)(dst + i);
        int p0 = atomicAdd(&g_cur[d.x], 1);
        int p1 = atomicAdd(&g_cur[d.y], 1);
        g_srcs[p0] = s.x;
        g_srcs[p1] = s.y;
    } else if (i < e) {
        int p = atomicAdd(&g_cur[dst[i]], 1);
        g_srcs[p] = src[i];
    }
}

// ---------------------------------------------------------------------------
// agg1: g_m1[d] = mean_{s in N(d)} x[s].  One WARP per dst node.
// Lanes 0..23 each own one float4 chunk; neighbor loop unrolled x4.
// ---------------------------------------------------------------------------
__global__ void agg1_kernel(const float4* __restrict__ x4, int n) {
    int w = (blockIdx.x * blockDim.x + threadIdx.x) >> 5;
    int lane = threadIdx.x & 31;
    if (w >= n || lane >= 24) return;
    int s0 = g_off[w], s1 = g_off[w + 1];
    float4 acc = make_float4(0.f, 0.f, 0.f, 0.f);
    int i = s0;
    for (; i + 3 < s1; i += 4) {
        int a = g_srcs[i], b = g_srcs[i+1], c = g_srcs[i+2], d = g_srcs[i+3];
        float4 va = x4[(size_t)a * 24 + lane];
        float4 vb = x4[(size_t)b * 24 + lane];
        float4 vc = x4[(size_t)c * 24 + lane];
        float4 vd = x4[(size_t)d * 24 + lane];
        acc.x += (va.x + vb.x) + (vc.x + vd.x);
        acc.y += (va.y + vb.y) + (vc.y + vd.y);
        acc.z += (va.z + vb.z) + (vc.z + vd.z);
        acc.w += (va.w + vb.w) + (vc.w + vd.w);
    }
    for (; i < s1; i++) {
        float4 va = x4[(size_t)g_srcs[i] * 24 + lane];
        acc.x += va.x; acc.y += va.y; acc.z += va.z; acc.w += va.w;
    }
    float inv = 1.0f / fmaxf((float)(s1 - s0), 1.0f);
    acc.x *= inv; acc.y *= inv; acc.z *= inv; acc.w *= inv;
    ((float4*)g_m1)[(size_t)w * 24 + lane] = acc;
}

// ---------------------------------------------------------------------------
// Layer 1 (tf32 TC GEMM + ELU), two-phase K staging for 2 blocks/SM:
//   phase 0: accumulate x @ w1_l^T ; phase 1: += m1 @ w1_r^T ; then bias+ELU.
// Block: 256 thr (8 warps), 128 nodes/tile, warp computes 16 nodes x 96.
// SMEM: A 128x100 (stride%32==4), B 96x104 (stride%32==8), bias 96 = 89.4KB.
// ---------------------------------------------------------------------------
#define L1_AS 100
#define L1_BS 104
__global__ __launch_bounds__(256, 2)
void layer1_tc(const float* __restrict__ x,
               const float* __restrict__ wl,
               const float* __restrict__ bl,
               const float* __restrict__ wr,
               int n) {
    extern __shared__ uint32_t smem1[];
    uint32_t* sA = smem1;                        // [128][100] tf32
    uint32_t* sB = sA + 128 * L1_AS;             // [96][104] tf32
    float* sbias = (float*)(sB + F1 * L1_BS);    // [96]

    const int tid = threadIdx.x;
    const int warp = tid >> 5;
    const int lane = tid & 31;
    const int gid = lane >> 2;     // 0..7
    const int tig = lane & 3;      // 0..3
    const int base = blockIdx.x * 128;
    const int row0 = warp * 16 + gid;

    if (tid < F1) sbias[tid] = bl[tid];

    float c[12][4];
    #pragma unroll
    for (int nt = 0; nt < 12; nt++)
        #pragma unroll
        for (int q = 0; q < 4; q++) c[nt][q] = 0.f;

    #pragma unroll
    for (int phase = 0; phase < 2; phase++) {
        const float* w = phase ? wr : wl;
        const float4* src4 = phase ? (const float4*)g_m1 : (const float4*)x;

        if (phase) __syncthreads();   // prior phase's reads complete

        // stage B: sB[k][f] = w[f][k]
        for (int i = tid; i < F1 * F1; i += 256) {
            int f = i / F1, k = i % F1;
            sB[k * L1_BS + f] = cvt_tf32(w[i]);
        }
        // stage A rows (zero-pad beyond n)
        for (int i = tid; i < 128 * 24; i += 256) {
            int r = i / 24, cc = i % 24;
            int g = base + r;
            float4 v = make_float4(0.f, 0.f, 0.f, 0.f);
            if (g < n) v = src4[(size_t)g * 24 + cc];
            uint32_t* pa = &sA[r * L1_AS + cc * 4];
            pa[0] = cvt_tf32(v.x); pa[1] = cvt_tf32(v.y);
            pa[2] = cvt_tf32(v.z); pa[3] = cvt_tf32(v.w);
        }
        __syncthreads();

        #pragma unroll 2
        for (int kb = 0; kb < 12; kb++) {
            int k0 = kb * 8;
            uint32_t a0 = sA[row0 * L1_AS + k0 + tig];
            uint32_t a1 = sA[(row0 + 8) * L1_AS + k0 + tig];
            uint32_t a2 = sA[row0 * L1_AS + k0 + tig + 4];
            uint32_t a3 = sA[(row0 + 8) * L1_AS + k0 + tig + 4];
            #pragma unroll
            for (int nt = 0; nt < 12; nt++) {
                uint32_t b0 = sB[(k0 + tig) * L1_BS + nt * 8 + gid];
                uint32_t b1 = sB[(k0 + tig + 4) * L1_BS + nt * 8 + gid];
                mma_tf32(c[nt], a0, a1, a2, a3, b0, b1);
            }
        }
    }

    // epilogue: bias + ELU, float2 stores (cols are pairs)
    int r0 = base + row0, r1 = r0 + 8;
    #pragma unroll
    for (int nt = 0; nt < 12; nt++) {
        int col = nt * 8 + tig * 2;
        float bi0 = sbias[col], bi1 = sbias[col + 1];
        if (r0 < n) {
            float2 o = make_float2(elu1(c[nt][0] + bi0), elu1(c[nt][1] + bi1));
            *(float2*)&g_h[(size_t)r0 * F1 + col] = o;
        }
        if (r1 < n) {
            float2 o = make_float2(elu1(c[nt][2] + bi0), elu1(c[nt][3] + bi1));
            *(float2*)&g_h[(size_t)r1 * F1 + col] = o;
        }
    }
}

// ---------------------------------------------------------------------------
// Layer 2 (tf32 TC GEMM, fused dual output):
//   [out_partial | y2] = h @ [w2_l^T | w2_r^T]   -- M x 96 x 128
// Block: 256 thr, 128 nodes/tile; cols 0..63 -> out (+bias), 64..127 -> y2.
// SMEM: A 128x100, B 96x136, bias 64 (~103.7KB, 2 blocks/SM).
// ---------------------------------------------------------------------------
#define L2_AS 100
#define L2_BS 136
__global__ __launch_bounds__(256, 2)
void layer2_tc(const float* __restrict__ wl,
               const float* __restrict__ bl,
               const float* __restrict__ wr,
               float* __restrict__ out,
               int n) {
    extern __shared__ uint32_t smem2[];
    uint32_t* sA = smem2;                        // [128][100]
    uint32_t* sB = sA + 128 * L2_AS;             // [96][136]
    float* sbias = (float*)(sB + F1 * L2_BS);    // [64]

    const int tid = threadIdx.x;
    const int warp = tid >> 5;
    const int lane = tid & 31;
    const int gid = lane >> 2;
    const int tig = lane & 3;
    const int base = blockIdx.x * 128;

    // stage B: sB[k][f] = w2l[f][k] (f<64), sB[k][64+f] = w2r[f][k]
    for (int i = tid; i < F2 * F1; i += 256) {
        int f = i / F1, k = i % F1;
        sB[k * L2_BS + f] = cvt_tf32(wl[i]);
        sB[k * L2_BS + F2 + f] = cvt_tf32(wr[i]);
    }
    if (tid < F2) sbias[tid] = bl[tid];

    // stage A: h rows (zero-pad)
    const float4* h4 = (const float4*)g_h;
    for (int i = tid; i < 128 * 24; i += 256) {
        int r = i / 24, cc = i % 24;
        int g = base + r;
        float4 v = make_float4(0.f, 0.f, 0.f, 0.f);
        if (g < n) v = h4[(size_t)g * 24 + cc];
        uint32_t* pa = &sA[r * L2_AS + cc * 4];
        pa[0] = cvt_tf32(v.x); pa[1] = cvt_tf32(v.y);
        pa[2] = cvt_tf32(v.z); pa[3] = cvt_tf32(v.w);
    }
    __syncthreads();

    float c[16][4];
    #pragma unroll
    for (int nt = 0; nt < 16; nt++)
        #pragma unroll
        for (int q = 0; q < 4; q++) c[nt][q] = 0.f;

    const int row0 = warp * 16 + gid;
    #pragma unroll 2
    for (int kb = 0; kb < 12; kb++) {
        int k0 = kb * 8;
        uint32_t a0 = sA[row0 * L2_AS + k0 + tig];
        uint32_t a1 = sA[(row0 + 8) * L2_AS + k0 + tig];
        uint32_t a2 = sA[row0 * L2_AS + k0 + tig + 4];
        uint32_t a3 = sA[(row0 + 8) * L2_AS + k0 + tig + 4];
        #pragma unroll
        for (int nt = 0; nt < 16; nt++) {
            uint32_t b0 = sB[(k0 + tig) * L2_BS + nt * 8 + gid];
            uint32_t b1 = sB[(k0 + tig + 4) * L2_BS + nt * 8 + gid];
            mma_tf32(c[nt], a0, a1, a2, a3, b0, b1);
        }
    }

    int r0 = base + row0, r1 = r0 + 8;
    #pragma unroll
    for (int nt = 0; nt < 16; nt++) {
        int col = nt * 8 + tig * 2;
        if (col < F2) {   // -> out with bias
            float bi0 = sbias[col], bi1 = sbias[col + 1];
            if (r0 < n)
                *(float2*)&out[(size_t)r0 * F2 + col] =
                    make_float2(c[nt][0] + bi0, c[nt][1] + bi1);
            if (r1 < n)
                *(float2*)&out[(size_t)r1 * F2 + col] =
                    make_float2(c[nt][2] + bi0, c[nt][3] + bi1);
        } else {          // -> y2
            int cy = col - F2;
            if (r0 < n)
                *(float2*)&g_y2[(size_t)r0 * F2 + cy] =
                    make_float2(c[nt][0], c[nt][1]);
            if (r1 < n)
                *(float2*)&g_y2[(size_t)r1 * F2 + cy] =
                    make_float2(c[nt][2], c[nt][3]);
        }
    }
}

// ---------------------------------------------------------------------------
// agg2 + final: out[d] += mean_nbr(y2). Half-warp per dst, unroll x4.
// ---------------------------------------------------------------------------
__global__ void agg2_kernel(float* __restrict__ out, int n) {
    int tid = blockIdx.x * blockDim.x + threadIdx.x;
    int d = tid >> 4;
    int lane = tid & 15;
    if (d >= n) return;
    int s0 = g_off[d], s1 = g_off[d + 1];
    const float4* y4 = (const float4*)g_y2;
    float4 acc = make_float4(0.f, 0.f, 0.f, 0.f);
    int i = s0;
    for (; i + 3 < s1; i += 4) {
        int a = g_srcs[i], b = g_srcs[i+1], c = g_srcs[i+2], dd = g_srcs[i+3];
        float4 va = y4[(size_t)a * 16 + lane];
        float4 vb = y4[(size_t)b * 16 + lane];
        float4 vc = y4[(size_t)c * 16 + lane];
        float4 vd = y4[(size_t)dd * 16 + lane];
        acc.x += (va.x + vb.x) + (vc.x + vd.x);
        acc.y += (va.y + vb.y) + (vc.y + vd.y);
        acc.z += (va.z + vb.z) + (vc.z + vd.z);
        acc.w += (va.w + vb.w) + (vc.w + vd.w);
    }
    for (; i < s1; i++) {
        float4 va = y4[(size_t)g_srcs[i] * 16 + lane];
        acc.x += va.x; acc.y += va.y; acc.z += va.z; acc.w += va.w;
    }
    float inv = 1.0f / fmaxf((float)(s1 - s0), 1.0f);
    float4* o = (float4*)out + (size_t)d * 16 + lane;
    float4 ov = *o;
    ov.x += acc.x * inv; ov.y += acc.y * inv;
    ov.z += acc.z * inv; ov.w += acc.w * inv;
    *o = ov;
}

// ---------------------------------------------------------------------------
extern "C" void kernel_launch(void* const* d_in, const int* in_sizes, int n_in,
                              void* d_out, int out_size) {
    const float* x   = (const float*)d_in[0];
    const int*   ei  = (const int*)d_in[1];   // [2, E] int32
    const float* w1l = (const float*)d_in[2];
    const float* b1l = (const float*)d_in[3];
    const float* w1r = (const float*)d_in[4];
    const float* w2l = (const float*)d_in[5];
    const float* b2l = (const float*)d_in[6];
    const float* w2r = (const float*)d_in[7];
    float* out = (float*)d_out;

    const int n = in_sizes[0] / F1;
    const int e = in_sizes[1] / 2;
    const int* src = ei;
    const int* dst = ei + e;

    const int l1_smem = (128 * L1_AS + F1 * L1_BS) * 4 + F1 * 4;   // ~89.4 KB
    const int l2_smem = (128 * L2_AS + F1 * L2_BS) * 4 + F2 * 4;   // ~103.7 KB
    cudaFuncSetAttribute(layer1_tc, cudaFuncAttributeMaxDynamicSharedMemorySize, l1_smem);
    cudaFuncSetAttribute(layer2_tc, cudaFuncAttributeMaxDynamicSharedMemorySize, l2_smem);

    // CSR build (g_deg enters zeroed; scan re-zeroes it)
    hist_kernel<<<(e / 4 + 255) / 256, 256>>>(dst, e);
    scan_kernel<<<1, SCAN_T>>>(n);
    scatter_kernel<<<(e / 2 + 255) / 256, 256>>>(src, dst, e);

    // layer-1 aggregation: one warp per dst node
    agg1_kernel<<<(n * 32 + 255) / 256, 256>>>((const float4*)x, n);

    // layer 1: tf32 TC GEMM + ELU (two-phase K)
    layer1_tc<<<(n + 127) / 128, 256, l1_smem>>>(x, w1l, b1l, w1r, n);

    // layer 2: tf32 TC GEMM (dual output)
    layer2_tc<<<(n + 127) / 128, 256, l2_smem>>>(w2l, b2l, w2r, out, n);

    // layer-2 aggregation + final combine
    long long threads = (long long)n * 16;
    agg2_kernel<<<(int)((threads + 255) / 256), 256>>>(out, n);
}

// round 10
// speedup vs baseline: 1.0079x; 1.0079x over previous
#include <cuda_runtime.h>
#include <math.h>
#include <stdint.h>

// Problem constants: N=50000, E=800000, F1=96, F2=64
#define MAXN 50000
#define MAXE 800000
#define F1 96
#define F2 64
#define SCAN_T 1024

// Scratch (device globals). __align__(16) for float4 access.
__device__ int g_deg[MAXN];          // starts zeroed (BSS); scan re-zeroes it
__device__ int g_off[MAXN + 1];
__device__ int g_cur[MAXN];
__device__ int g_srcs[MAXE];
__device__ __align__(16) float g_m1[MAXN * F1];   // mean of x over neighbors
__device__ __align__(16) float g_h [MAXN * F1];   // layer-1 output
__device__ __align__(16) float g_y2[MAXN * F2];   // h @ w2_r^T

// ---------------------------------------------------------------------------
// tf32 helpers
// ---------------------------------------------------------------------------
__device__ __forceinline__ uint32_t cvt_tf32(float f) {
    uint32_t u;
    asm("cvt.rna.tf32.f32 %0, %1;" : "=r"(u) : "f"(f));
    return u;
}

__device__ __forceinline__ uint4 cvt4(float4 v) {
    return make_uint4(cvt_tf32(v.x), cvt_tf32(v.y), cvt_tf32(v.z), cvt_tf32(v.w));
}

__device__ __forceinline__ void mma_tf32(float* c,
                                         uint32_t a0, uint32_t a1,
                                         uint32_t a2, uint32_t a3,
                                         uint32_t b0, uint32_t b1) {
    asm volatile(
        "mma.sync.aligned.m16n8k8.row.col.f32.tf32.tf32.f32 "
        "{%0,%1,%2,%3}, {%4,%5,%6,%7}, {%8,%9}, {%0,%1,%2,%3};"
        : "+f"(c[0]), "+f"(c[1]), "+f"(c[2]), "+f"(c[3])
        : "r"(a0), "r"(a1), "r"(a2), "r"(a3), "r"(b0), "r"(b1));
}

__device__ __forceinline__ float elu1(float v) {
    return v > 0.f ? v : (__expf(v) - 1.0f);
}

// ---------------------------------------------------------------------------
// CSR build: histogram -> scan (clears g_deg) -> scatter
// ---------------------------------------------------------------------------
__global__ void hist_kernel(const int* __restrict__ dst, int e) {
    int i4 = (blockIdx.x * blockDim.x + threadIdx.x) * 4;
    if (i4 + 3 < e) {
        int4 d = *(const int4*)(dst + i4);
        atomicAdd(&g_deg[d.x], 1);
        atomicAdd(&g_deg[d.y], 1);
        atomicAdd(&g_deg[d.z], 1);
        atomicAdd(&g_deg[d.w], 1);
    } else {
        for (int i = i4; i < e; i++) atomicAdd(&g_deg[dst[i]], 1);
    }
}

__global__ void scan_kernel(int n) {
    __shared__ int ssum[SCAN_T];
    int t = threadIdx.x;
    int chunk = (n + SCAN_T - 1) / SCAN_T;
    int start = t * chunk;
    int end = min(start + chunk, n);
    int local = 0;
    for (int i = start; i < end; i++) local += g_deg[i];
    ssum[t] = local;
    __syncthreads();
    for (int ofs = 1; ofs < SCAN_T; ofs <<= 1) {
        int v = (t >= ofs) ? ssum[t - ofs] : 0;
        __syncthreads();
        ssum[t] += v;
        __syncthreads();
    }
    int run = ssum[t] - local;   // exclusive prefix
    for (int i = start; i < end; i++) {
        int d = g_deg[i];
        g_off[i] = run;
        g_cur[i] = run;
        run += d;
        g_deg[i] = 0;            // leave cleared for the next launch
    }
    if (t == SCAN_T - 1) g_off[n] = ssum[SCAN_T - 1];
}

__global__ void scatter_kernel(const int* __restrict__ src,
                               const int* __restrict__ dst, int e) {
    int i = (blockIdx.x * blockDim.x + threadIdx.x) * 2;
    if (i + 1 < e) {
        int2 s = *(const int2*)(src + i);
        int2 d = *(const int2*)(dst + i);
        int p0 = atomicAdd(&g_cur[d.x], 1);
        int p1 = atomicAdd(&g_cur[d.y], 1);
        g_srcs[p0] = s.x;
        g_srcs[p1] = s.y;
    } else if (i < e) {
        int p = atomicAdd(&g_cur[dst[i]], 1);
        g_srcs[p] = src[i];
    }
}

// ---------------------------------------------------------------------------
// agg1: g_m1[d] = mean_{s in N(d)} x[s].  One WARP per dst node.
// Lanes 0..23 each own one float4 chunk; neighbor loop unrolled x4.
// ---------------------------------------------------------------------------
__global__ void agg1_kernel(const float4* __restrict__ x4, int n) {
    int w = (blockIdx.x * blockDim.x + threadIdx.x) >> 5;
    int lane = threadIdx.x & 31;
    if (w >= n || lane >= 24) return;
    int s0 = g_off[w], s1 = g_off[w + 1];
    float4 acc = make_float4(0.f, 0.f, 0.f, 0.f);
    int i = s0;
    for (; i + 3 < s1; i += 4) {
        int a = g_srcs[i], b = g_srcs[i+1], c = g_srcs[i+2], d = g_srcs[i+3];
        float4 va = x4[(size_t)a * 24 + lane];
        float4 vb = x4[(size_t)b * 24 + lane];
        float4 vc = x4[(size_t)c * 24 + lane];
        float4 vd = x4[(size_t)d * 24 + lane];
        acc.x += (va.x + vb.x) + (vc.x + vd.x);
        acc.y += (va.y + vb.y) + (vc.y + vd.y);
        acc.z += (va.z + vb.z) + (vc.z + vd.z);
        acc.w += (va.w + vb.w) + (vc.w + vd.w);
    }
    for (; i < s1; i++) {
        float4 va = x4[(size_t)g_srcs[i] * 24 + lane];
        acc.x += va.x; acc.y += va.y; acc.z += va.z; acc.w += va.w;
    }
    float inv = 1.0f / fmaxf((float)(s1 - s0), 1.0f);
    acc.x *= inv; acc.y *= inv; acc.z *= inv; acc.w *= inv;
    ((float4*)g_m1)[(size_t)w * 24 + lane] = acc;
}

// ---------------------------------------------------------------------------
// Layer 1 (tf32 TC GEMM + ELU), single-phase:
//   h = elu([x | m1] @ [w1_l | w1_r]^T + b1)   -- M x 192 x 96
// Block: 256 thr, 128 nodes/tile; warp computes 16 rows x 96 cols.
// SMEM: A[128][196] (stride%32==4), B[96][196] natural [n][k] layout
//   (B-frag b0 at (k=tig, n=gid): addr (8nt+gid)*196 + k0+tig -> 4*gid+tig
//    conflict-free). All staging stores are uint4 (offsets 16B-aligned).
// ---------------------------------------------------------------------------
#define L1_AS 196
#define L1_WS 196
__global__ __launch_bounds__(256, 1)
void layer1_tc(const float* __restrict__ x,
               const float* __restrict__ wl,
               const float* __restrict__ bl,
               const float* __restrict__ wr,
               int n) {
    extern __shared__ uint32_t smem1[];
    uint32_t* sA = smem1;                        // [128][196]
    uint32_t* sB = sA + 128 * L1_AS;             // [96][196] natural [n][k]
    float* sbias = (float*)(sB + F1 * L1_WS);    // [96]

    const int tid = threadIdx.x;
    const int warp = tid >> 5;
    const int lane = tid & 31;
    const int gid = lane >> 2;
    const int tig = lane & 3;
    const int base = blockIdx.x * 128;
    const int row0 = warp * 16 + gid;

    // stage B (row copy, vectorized): sB[f][0..95]=wl[f], sB[f][96..191]=wr[f]
    const float4* wl4 = (const float4*)wl;
    const float4* wr4 = (const float4*)wr;
    for (int i = tid; i < F1 * 24; i += 256) {
        int f = i / 24, c = i % 24;
        *(uint4*)&sB[f * L1_WS + c * 4]      = cvt4(wl4[f * 24 + c]);
        *(uint4*)&sB[f * L1_WS + F1 + c * 4] = cvt4(wr4[f * 24 + c]);
    }
    if (tid < F1) sbias[tid] = bl[tid];

    // stage A (vectorized): cols 0..95 = x, 96..191 = m1
    const float4* x4 = (const float4*)x;
    const float4* m4 = (const float4*)g_m1;
    for (int i = tid; i < 128 * 24; i += 256) {
        int r = i / 24, c = i % 24;
        int g = base + r;
        float4 vx = make_float4(0.f, 0.f, 0.f, 0.f);
        float4 vm = vx;
        if (g < n) { vx = x4[(size_t)g * 24 + c]; vm = m4[(size_t)g * 24 + c]; }
        *(uint4*)&sA[r * L1_AS + c * 4]      = cvt4(vx);
        *(uint4*)&sA[r * L1_AS + F1 + c * 4] = cvt4(vm);
    }
    __syncthreads();

    float c[12][4];
    #pragma unroll
    for (int nt = 0; nt < 12; nt++)
        #pragma unroll
        for (int q = 0; q < 4; q++) c[nt][q] = 0.f;

    #pragma unroll 2
    for (int kb = 0; kb < 24; kb++) {
        int k0 = kb * 8;
        uint32_t a0 = sA[row0 * L1_AS + k0 + tig];
        uint32_t a1 = sA[(row0 + 8) * L1_AS + k0 + tig];
        uint32_t a2 = sA[row0 * L1_AS + k0 + tig + 4];
        uint32_t a3 = sA[(row0 + 8) * L1_AS + k0 + tig + 4];
        #pragma unroll
        for (int nt = 0; nt < 12; nt++) {
            uint32_t b0 = sB[(nt * 8 + gid) * L1_WS + k0 + tig];
            uint32_t b1 = sB[(nt * 8 + gid) * L1_WS + k0 + tig + 4];
            mma_tf32(c[nt], a0, a1, a2, a3, b0, b1);
        }
    }

    // epilogue: bias + ELU, float2 stores
    int r0 = base + row0, r1 = r0 + 8;
    #pragma unroll
    for (int nt = 0; nt < 12; nt++) {
        int col = nt * 8 + tig * 2;
        float bi0 = sbias[col], bi1 = sbias[col + 1];
        if (r0 < n)
            *(float2*)&g_h[(size_t)r0 * F1 + col] =
                make_float2(elu1(c[nt][0] + bi0), elu1(c[nt][1] + bi1));
        if (r1 < n)
            *(float2*)&g_h[(size_t)r1 * F1 + col] =
                make_float2(elu1(c[nt][2] + bi0), elu1(c[nt][3] + bi1));
    }
}

// ---------------------------------------------------------------------------
// Layer 2 (tf32 TC GEMM, fused dual output):
//   [out_partial | y2] = h @ [w2_l^T | w2_r^T]   -- M x 96 x 128
// SMEM: A[128][100], B[128][100] natural [n][k]; ~100.3KB -> 2 blocks/SM.
// ---------------------------------------------------------------------------
#define L2_AS 100
#define L2_WS 100
__global__ __launch_bounds__(256, 2)
void layer2_tc(const float* __restrict__ wl,
               const float* __restrict__ bl,
               const float* __restrict__ wr,
               float* __restrict__ out,
               int n) {
    extern __shared__ uint32_t smem2[];
    uint32_t* sA = smem2;                        // [128][100]
    uint32_t* sB = sA + 128 * L2_AS;             // [128][100]: rows 0..63 wl, 64..127 wr
    float* sbias = (float*)(sB + 128 * L2_WS);   // [64]

    const int tid = threadIdx.x;
    const int warp = tid >> 5;
    const int lane = tid & 31;
    const int gid = lane >> 2;
    const int tig = lane & 3;
    const int base = blockIdx.x * 128;
    const int row0 = warp * 16 + gid;

    // stage B (vectorized row copy)
    const float4* wl4 = (const float4*)wl;
    const float4* wr4 = (const float4*)wr;
    for (int i = tid; i < 128 * 24; i += 256) {
        int nr = i / 24, c = i % 24;
        float4 v = (nr < F2) ? wl4[nr * 24 + c] : wr4[(nr - F2) * 24 + c];
        *(uint4*)&sB[nr * L2_WS + c * 4] = cvt4(v);
    }
    if (tid < F2) sbias[tid] = bl[tid];

    // stage A (vectorized)
    const float4* h4 = (const float4*)g_h;
    for (int i = tid; i < 128 * 24; i += 256) {
        int r = i / 24, c = i % 24;
        int g = base + r;
        float4 v = make_float4(0.f, 0.f, 0.f, 0.f);
        if (g < n) v = h4[(size_t)g * 24 + c];
        *(uint4*)&sA[r * L2_AS + c * 4] = cvt4(v);
    }
    __syncthreads();

    float c[16][4];
    #pragma unroll
    for (int nt = 0; nt < 16; nt++)
        #pragma unroll
        for (int q = 0; q < 4; q++) c[nt][q] = 0.f;

    #pragma unroll 2
    for (int kb = 0; kb < 12; kb++) {
        int k0 = kb * 8;
        uint32_t a0 = sA[row0 * L2_AS + k0 + tig];
        uint32_t a1 = sA[(row0 + 8) * L2_AS + k0 + tig];
        uint32_t a2 = sA[row0 * L2_AS + k0 + tig + 4];
        uint32_t a3 = sA[(row0 + 8) * L2_AS + k0 + tig + 4];
        #pragma unroll
        for (int nt = 0; nt < 16; nt++) {
            uint32_t b0 = sB[(nt * 8 + gid) * L2_WS + k0 + tig];
            uint32_t b1 = sB[(nt * 8 + gid) * L2_WS + k0 + tig + 4];
            mma_tf32(c[nt], a0, a1, a2, a3, b0, b1);
        }
    }

    int r0 = base + row0, r1 = r0 + 8;
    #pragma unroll
    for (int nt = 0; nt < 16; nt++) {
        int col = nt * 8 + tig * 2;
        if (col < F2) {   // -> out with bias
            float bi0 = sbias[col], bi1 = sbias[col + 1];
            if (r0 < n)
                *(float2*)&out[(size_t)r0 * F2 + col] =
                    make_float2(c[nt][0] + bi0, c[nt][1] + bi1);
            if (r1 < n)
                *(float2*)&out[(size_t)r1 * F2 + col] =
                    make_float2(c[nt][2] + bi0, c[nt][3] + bi1);
        } else {          // -> y2
            int cy = col - F2;
            if (r0 < n)
                *(float2*)&g_y2[(size_t)r0 * F2 + cy] =
                    make_float2(c[nt][0], c[nt][1]);
            if (r1 < n)
                *(float2*)&g_y2[(size_t)r1 * F2 + cy] =
                    make_float2(c[nt][2], c[nt][3]);
        }
    }
}

// ---------------------------------------------------------------------------
// agg2 + final: out[d] += mean_nbr(y2). Half-warp per dst, unroll x4.
// ---------------------------------------------------------------------------
__global__ void agg2_kernel(float* __restrict__ out, int n) {
    int tid = blockIdx.x * blockDim.x + threadIdx.x;
    int d = tid >> 4;
    int lane = tid & 15;
    if (d >= n) return;
    int s0 = g_off[d], s1 = g_off[d + 1];
    const float4* y4 = (const float4*)g_y2;
    float4 acc = make_float4(0.f, 0.f, 0.f, 0.f);
    int i = s0;
    for (; i + 3 < s1; i += 4) {
        int a = g_srcs[i], b = g_srcs[i+1], c = g_srcs[i+2], dd = g_srcs[i+3];
        float4 va = y4[(size_t)a * 16 + lane];
        float4 vb = y4[(size_t)b * 16 + lane];
        float4 vc = y4[(size_t)c * 16 + lane];
        float4 vd = y4[(size_t)dd * 16 + lane];
        acc.x += (va.x + vb.x) + (vc.x + vd.x);
        acc.y += (va.y + vb.y) + (vc.y + vd.y);
        acc.z += (va.z + vb.z) + (vc.z + vd.z);
        acc.w += (va.w + vb.w) + (vc.w + vd.w);
    }
    for (; i < s1; i++) {
        float4 va = y4[(size_t)g_srcs[i] * 16 + lane];
        acc.x += va.x; acc.y += va.y; acc.z += va.z; acc.w += va.w;
    }
    float inv = 1.0f / fmaxf((float)(s1 - s0), 1.0f);
    float4* o = (float4*)out + (size_t)d * 16 + lane;
    float4 ov = *o;
    ov.x += acc.x * inv; ov.y += acc.y * inv;
    ov.z += acc.z * inv; ov.w += acc.w * inv;
    *o = ov;
}

// ---------------------------------------------------------------------------
extern "C" void kernel_launch(void* const* d_in, const int* in_sizes, int n_in,
                              void* d_out, int out_size) {
    const float* x   = (const float*)d_in[0];
    const int*   ei  = (const int*)d_in[1];   // [2, E] int32
    const float* w1l = (const float*)d_in[2];
    const float* b1l = (const float*)d_in[3];
    const float* w1r = (const float*)d_in[4];
    const float* w2l = (const float*)d_in[5];
    const float* b2l = (const float*)d_in[6];
    const float* w2r = (const float*)d_in[7];
    float* out = (float*)d_out;

    const int n = in_sizes[0] / F1;
    const int e = in_sizes[1] / 2;
    const int* src = ei;
    const int* dst = ei + e;

    const int l1_smem = (128 * L1_AS + F1 * L1_WS) * 4 + F1 * 4;   // ~172 KB
    const int l2_smem = (128 * L2_AS + 128 * L2_WS) * 4 + F2 * 4;  // ~100.3 KB
    cudaFuncSetAttribute(layer1_tc, cudaFuncAttributeMaxDynamicSharedMemorySize, l1_smem);
    cudaFuncSetAttribute(layer2_tc, cudaFuncAttributeMaxDynamicSharedMemorySize, l2_smem);

    // CSR build (g_deg enters zeroed; scan re-zeroes it)
    hist_kernel<<<(e / 4 + 255) / 256, 256>>>(dst, e);
    scan_kernel<<<1, SCAN_T>>>(n);
    scatter_kernel<<<(e / 2 + 255) / 256, 256>>>(src, dst, e);

    // layer-1 aggregation: one warp per dst node
    agg1_kernel<<<(n * 32 + 255) / 256, 256>>>((const float4*)x, n);

    // layer 1: tf32 TC GEMM + ELU
    layer1_tc<<<(n + 127) / 128, 256, l1_smem>>>(x, w1l, b1l, w1r, n);

    // layer 2: tf32 TC GEMM (dual output)
    layer2_tc<<<(n + 127) / 128, 256, l2_smem>>>(w2l, b2l, w2r, out, n);

    // layer-2 aggregation + final combine
    long long threads = (long long)n * 16;
    agg2_kernel<<<(int)((threads + 255) / 256), 256>>>(out, n);
}

// round 12
// speedup vs baseline: 1.5045x; 1.4927x over previous
#include <cuda_runtime.h>
#include <math.h>
#include <stdint.h>

// Problem constants: N=50000, E=800000, F1=96, F2=64
#define MAXN 50000
#define MAXE 800000
#define F1 96
#define F2 64
#define SCAN_T 1024
#define SCAN_C 52              // elements per scan thread (multiple of 4)

// Scratch (device globals). __align__(16) for int4/float4 access.
__device__ __align__(16) int g_deg[MAXN];   // BSS-zero; scan re-zeroes it
__device__ __align__(16) int g_off[MAXN + 1];
__device__ int g_srcs[MAXE];
__device__ __align__(16) float g_m1[MAXN * F1];   // mean of x over neighbors
__device__ __align__(16) float g_h [MAXN * F1];   // layer-1 output
__device__ __align__(16) float g_y2[MAXN * F2];   // h @ w2_r^T

// ---------------------------------------------------------------------------
// tf32 helpers
// ---------------------------------------------------------------------------
__device__ __forceinline__ uint32_t cvt_tf32(float f) {
    uint32_t u;
    asm("cvt.rna.tf32.f32 %0, %1;" : "=r"(u) : "f"(f));
    return u;
}

__device__ __forceinline__ uint4 cvt4(float4 v) {
    return make_uint4(cvt_tf32(v.x), cvt_tf32(v.y), cvt_tf32(v.z), cvt_tf32(v.w));
}

__device__ __forceinline__ void mma_tf32(float* c,
                                         uint32_t a0, uint32_t a1,
                                         uint32_t a2, uint32_t a3,
                                         uint32_t b0, uint32_t b1) {
    asm volatile(
        "mma.sync.aligned.m16n8k8.row.col.f32.tf32.tf32.f32 "
        "{%0,%1,%2,%3}, {%4,%5,%6,%7}, {%8,%9}, {%0,%1,%2,%3};"
        : "+f"(c[0]), "+f"(c[1]), "+f"(c[2]), "+f"(c[3])
        : "r"(a0), "r"(a1), "r"(a2), "r"(a3), "r"(b0), "r"(b1));
}

__device__ __forceinline__ float elu1(float v) {
    return v > 0.f ? v : (__expf(v) - 1.0f);
}

// ---------------------------------------------------------------------------
// CSR build: histogram -> vectorized scan (clears g_deg) -> scatter
// Post-scatter convention: segment(d) = [d ? g_off[d-1] : 0, g_off[d])
// ---------------------------------------------------------------------------
__global__ void hist_kernel(const int* __restrict__ dst, int e) {
    int i4 = (blockIdx.x * blockDim.x + threadIdx.x) * 4;
    if (i4 + 3 < e) {
        int4 d = *(const int4*)(dst + i4);
        atomicAdd(&g_deg[d.x], 1);
        atomicAdd(&g_deg[d.y], 1);
        atomicAdd(&g_deg[d.z], 1);
        atomicAdd(&g_deg[d.w], 1);
    } else {
        for (int i = i4; i < e; i++) atomicAdd(&g_deg[dst[i]], 1);
    }
}

__global__ void scan_kernel(int n) {
    __shared__ int ssum[SCAN_T];
    const int t = threadIdx.x;
    const int start = t * SCAN_C;
    const int end = min(start + SCAN_C, n);

    // 1) vectorized local sum
    int local = 0;
    #pragma unroll
    for (int j = 0; j < SCAN_C / 4; j++) {
        int idx = start + j * 4;
        if (idx + 3 < end) {
            int4 d = *(const int4*)(g_deg + idx);
            local += d.x + d.y + d.z + d.w;
        } else {
            for (int i = idx; i < end; i++) local += g_deg[i];
            break;
        }
    }
    ssum[t] = local;
    __syncthreads();

    // 2) block scan
    for (int ofs = 1; ofs < SCAN_T; ofs <<= 1) {
        int v = (t >= ofs) ? ssum[t - ofs] : 0;
        __syncthreads();
        ssum[t] += v;
        __syncthreads();
    }
    int run = ssum[t] - local;   // exclusive prefix of this thread's chunk

    // 3) vectorized write of exclusive offsets + clear g_deg
    #pragma unroll
    for (int j = 0; j < SCAN_C / 4; j++) {
        int idx = start + j * 4;
        if (idx + 3 < end) {
            int4 d = *(const int4*)(g_deg + idx);
            int4 o;
            o.x = run;            run += d.x;
            o.y = run;            run += d.y;
            o.z = run;            run += d.z;
            o.w = run;            run += d.w;
            *(int4*)(g_off + idx) = o;
            *(int4*)(g_deg + idx) = make_int4(0, 0, 0, 0);
        } else {
            for (int i = idx; i < end; i++) {
                int d = g_deg[i];
                g_off[i] = run;
                run += d;
                g_deg[i] = 0;
            }
            break;
        }
    }
    if (t == SCAN_T - 1) g_off[n] = ssum[SCAN_T - 1];
}

__global__ void scatter_kernel(const int* __restrict__ src,
                               const int* __restrict__ dst, int e) {
    int i = (blockIdx.x * blockDim.x + threadIdx.x) * 2;
    if (i + 1 < e) {
        int2 s = *(const int2*)(src + i);
        int2 d = *(const int2*)(dst + i);
        int p0 = atomicAdd(&g_off[d.x], 1);
        int p1 = atomicAdd(&g_off[d.y], 1);
        g_srcs[p0] = s.x;
        g_srcs[p1] = s.y;
    } else if (i < e) {
        int p = atomicAdd(&g_off[dst[i]], 1);
        g_srcs[p] = src[i];
    }
}

// ---------------------------------------------------------------------------
// agg1: g_m1[d] = mean_{s in N(d)} x[s].
// Lane-dense: 24 threads per node (thread = (node, float4-chunk)),
// 192-thread blocks = 8 nodes/block; neighbor loop unrolled x4.
// ---------------------------------------------------------------------------
__global__ void agg1_kernel(const float4* __restrict__ x4, int n) {
    int node = blockIdx.x * 8 + threadIdx.x / 24;
    int lane = threadIdx.x % 24;
    if (node >= n) return;
    int s0 = node ? g_off[node - 1] : 0;
    int s1 = g_off[node];
    float4 acc = make_float4(0.f, 0.f, 0.f, 0.f);
    int i = s0;
    for (; i + 3 < s1; i += 4) {
        int a = g_srcs[i], b = g_srcs[i+1], c = g_srcs[i+2], d = g_srcs[i+3];
        float4 va = x4[(size_t)a * 24 + lane];
        float4 vb = x4[(size_t)b * 24 + lane];
        float4 vc = x4[(size_t)c * 24 + lane];
        float4 vd = x4[(size_t)d * 24 + lane];
        acc.x += (va.x + vb.x) + (vc.x + vd.x);
        acc.y += (va.y + vb.y) + (vc.y + vd.y);
        acc.z += (va.z + vb.z) + (vc.z + vd.z);
        acc.w += (va.w + vb.w) + (vc.w + vd.w);
    }
    for (; i < s1; i++) {
        float4 va = x4[(size_t)g_srcs[i] * 24 + lane];
        acc.x += va.x; acc.y += va.y; acc.z += va.z; acc.w += va.w;
    }
    float inv = 1.0f / fmaxf((float)(s1 - s0), 1.0f);
    acc.x *= inv; acc.y *= inv; acc.z *= inv; acc.w *= inv;
    ((float4*)g_m1)[(size_t)node * 24 + lane] = acc;
}

// ---------------------------------------------------------------------------
// Layer 1 (tf32 TC GEMM + ELU), single-phase:
//   h = elu([x | m1] @ [w1_l | w1_r]^T + b1)   -- M x 192 x 96
// SMEM: A[128][196], B[96][196] natural [n][k]; uint4 staging.
// ---------------------------------------------------------------------------
#define L1_AS 196
#define L1_WS 196
__global__ __launch_bounds__(256, 1)
void layer1_tc(const float* __restrict__ x,
               const float* __restrict__ wl,
               const float* __restrict__ bl,
               const float* __restrict__ wr,
               int n) {
    extern __shared__ uint32_t smem1[];
    uint32_t* sA = smem1;                        // [128][196]
    uint32_t* sB = sA + 128 * L1_AS;             // [96][196] natural [n][k]
    float* sbias = (float*)(sB + F1 * L1_WS);    // [96]

    const int tid = threadIdx.x;
    const int warp = tid >> 5;
    const int lane = tid & 31;
    const int gid = lane >> 2;
    const int tig = lane & 3;
    const int base = blockIdx.x * 128;
    const int row0 = warp * 16 + gid;

    const float4* wl4 = (const float4*)wl;
    const float4* wr4 = (const float4*)wr;
    for (int i = tid; i < F1 * 24; i += 256) {
        int f = i / 24, c = i % 24;
        *(uint4*)&sB[f * L1_WS + c * 4]      = cvt4(wl4[f * 24 + c]);
        *(uint4*)&sB[f * L1_WS + F1 + c * 4] = cvt4(wr4[f * 24 + c]);
    }
    if (tid < F1) sbias[tid] = bl[tid];

    const float4* x4 = (const float4*)x;
    const float4* m4 = (const float4*)g_m1;
    for (int i = tid; i < 128 * 24; i += 256) {
        int r = i / 24, c = i % 24;
        int g = base + r;
        float4 vx = make_float4(0.f, 0.f, 0.f, 0.f);
        float4 vm = vx;
        if (g < n) { vx = x4[(size_t)g * 24 + c]; vm = m4[(size_t)g * 24 + c]; }
        *(uint4*)&sA[r * L1_AS + c * 4]      = cvt4(vx);
        *(uint4*)&sA[r * L1_AS + F1 + c * 4] = cvt4(vm);
    }
    __syncthreads();

    float c[12][4];
    #pragma unroll
    for (int nt = 0; nt < 12; nt++)
        #pragma unroll
        for (int q = 0; q < 4; q++) c[nt][q] = 0.f;

    #pragma unroll 2
    for (int kb = 0; kb < 24; kb++) {
        int k0 = kb * 8;
        uint32_t a0 = sA[row0 * L1_AS + k0 + tig];
        uint32_t a1 = sA[(row0 + 8) * L1_AS + k0 + tig];
        uint32_t a2 = sA[row0 * L1_AS + k0 + tig + 4];
        uint32_t a3 = sA[(row0 + 8) * L1_AS + k0 + tig + 4];
        #pragma unroll
        for (int nt = 0; nt < 12; nt++) {
            uint32_t b0 = sB[(nt * 8 + gid) * L1_WS + k0 + tig];
            uint32_t b1 = sB[(nt * 8 + gid) * L1_WS + k0 + tig + 4];
            mma_tf32(c[nt], a0, a1, a2, a3, b0, b1);
        }
    }

    int r0 = base + row0, r1 = r0 + 8;
    #pragma unroll
    for (int nt = 0; nt < 12; nt++) {
        int col = nt * 8 + tig * 2;
        float bi0 = sbias[col], bi1 = sbias[col + 1];
        if (r0 < n)
            *(float2*)&g_h[(size_t)r0 * F1 + col] =
                make_float2(elu1(c[nt][0] + bi0), elu1(c[nt][1] + bi1));
        if (r1 < n)
            *(float2*)&g_h[(size_t)r1 * F1 + col] =
                make_float2(elu1(c[nt][2] + bi0), elu1(c[nt][3] + bi1));
    }
}

// ---------------------------------------------------------------------------
// Layer 2 (tf32 TC GEMM, fused dual output):
//   [out_partial | y2] = h @ [w2_l^T | w2_r^T]   -- M x 96 x 128
// SMEM: A[128][100], B[128][100] natural [n][k]; ~100.3KB -> 2 blocks/SM.
// ---------------------------------------------------------------------------
#define L2_AS 100
#define L2_WS 100
__global__ __launch_bounds__(256, 2)
void layer2_tc(const float* __restrict__ wl,
               const float* __restrict__ bl,
               const float* __restrict__ wr,
               float* __restrict__ out,
               int n) {
    extern __shared__ uint32_t smem2[];
    uint32_t* sA = smem2;                        // [128][100]
    uint32_t* sB = sA + 128 * L2_AS;             // [128][100]: rows 0..63 wl, 64..127 wr
    float* sbias = (float*)(sB + 128 * L2_WS);   // [64]

    const int tid = threadIdx.x;
    const int warp = tid >> 5;
    const int lane = tid & 31;
    const int gid = lane >> 2;
    const int tig = lane & 3;
    const int base = blockIdx.x * 128;
    const int row0 = warp * 16 + gid;

    const float4* wl4 = (const float4*)wl;
    const float4* wr4 = (const float4*)wr;
    for (int i = tid; i < 128 * 24; i += 256) {
        int nr = i / 24, c = i % 24;
        float4 v = (nr < F2) ? wl4[nr * 24 + c] : wr4[(nr - F2) * 24 + c];
        *(uint4*)&sB[nr * L2_WS + c * 4] = cvt4(v);
    }
    if (tid < F2) sbias[tid] = bl[tid];

    const float4* h4 = (const float4*)g_h;
    for (int i = tid; i < 128 * 24; i += 256) {
        int r = i / 24, c = i % 24;
        int g = base + r;
        float4 v = make_float4(0.f, 0.f, 0.f, 0.f);
        if (g < n) v = h4[(size_t)g * 24 + c];
        *(uint4*)&sA[r * L2_AS + c * 4] = cvt4(v);
    }
    __syncthreads();

    float c[16][4];
    #pragma unroll
    for (int nt = 0; nt < 16; nt++)
        #pragma unroll
        for (int q = 0; q < 4; q++) c[nt][q] = 0.f;

    #pragma unroll 2
    for (int kb = 0; kb < 12; kb++) {
        int k0 = kb * 8;
        uint32_t a0 = sA[row0 * L2_AS + k0 + tig];
        uint32_t a1 = sA[(row0 + 8) * L2_AS + k0 + tig];
        uint32_t a2 = sA[row0 * L2_AS + k0 + tig + 4];
        uint32_t a3 = sA[(row0 + 8) * L2_AS + k0 + tig + 4];
        #pragma unroll
        for (int nt = 0; nt < 16; nt++) {
            uint32_t b0 = sB[(nt * 8 + gid) * L2_WS + k0 + tig];
            uint32_t b1 = sB[(nt * 8 + gid) * L2_WS + k0 + tig + 4];
            mma_tf32(c[nt], a0, a1, a2, a3, b0, b1);
        }
    }

    int r0 = base + row0, r1 = r0 + 8;
    #pragma unroll
    for (int nt = 0; nt < 16; nt++) {
        int col = nt * 8 + tig * 2;
        if (col < F2) {
            float bi0 = sbias[col], bi1 = sbias[col + 1];
            if (r0 < n)
                *(float2*)&out[(size_t)r0 * F2 + col] =
                    make_float2(c[nt][0] + bi0, c[nt][1] + bi1);
            if (r1 < n)
                *(float2*)&out[(size_t)r1 * F2 + col] =
                    make_float2(c[nt][2] + bi0, c[nt][3] + bi1);
        } else {
            int cy = col - F2;
            if (r0 < n)
                *(float2*)&g_y2[(size_t)r0 * F2 + cy] =
                    make_float2(c[nt][0], c[nt][1]);
            if (r1 < n)
                *(float2*)&g_y2[(size_t)r1 * F2 + cy] =
                    make_float2(c[nt][2], c[nt][3]);
        }
    }
}

// ---------------------------------------------------------------------------
// agg2 + final: out[d] += mean_nbr(y2). 16 threads per dst, unroll x4.
// ---------------------------------------------------------------------------
__global__ void agg2_kernel(float* __restrict__ out, int n) {
    int tid = blockIdx.x * blockDim.x + threadIdx.x;
    int d = tid >> 4;
    int lane = tid & 15;
    if (d >= n) return;
    int s0 = d ? g_off[d - 1] : 0;
    int s1 = g_off[d];
    const float4* y4 = (const float4*)g_y2;
    float4 acc = make_float4(0.f, 0.f, 0.f, 0.f);
    int i = s0;
    for (; i + 3 < s1; i += 4) {
        int a = g_srcs[i], b = g_srcs[i+1], c = g_srcs[i+2], dd = g_srcs[i+3];
        float4 va = y4[(size_t)a * 16 + lane];
        float4 vb = y4[(size_t)b * 16 + lane];
        float4 vc = y4[(size_t)c * 16 + lane];
        float4 vd = y4[(size_t)dd * 16 + lane];
        acc.x += (va.x + vb.x) + (vc.x + vd.x);
        acc.y += (va.y + vb.y) + (vc.y + vd.y);
        acc.z += (va.z + vb.z) + (vc.z + vd.z);
        acc.w += (va.w + vb.w) + (vc.w + vd.w);
    }
    for (; i < s1; i++) {
        float4 va = y4[(size_t)g_srcs[i] * 16 + lane];
        acc.x += va.x; acc.y += va.y; acc.z += va.z; acc.w += va.w;
    }
    float inv = 1.0f / fmaxf((float)(s1 - s0), 1.0f);
    float4* o = (float4*)out + (size_t)d * 16 + lane;
    float4 ov = *o;
    ov.x += acc.x * inv; ov.y += acc.y * inv;
    ov.z += acc.z * inv; ov.w += acc.w * inv;
    *o = ov;
}

// ---------------------------------------------------------------------------
extern "C" void kernel_launch(void* const* d_in, const int* in_sizes, int n_in,
                              void* d_out, int out_size) {
    const float* x   = (const float*)d_in[0];
    const int*   ei  = (const int*)d_in[1];   // [2, E] int32
    const float* w1l = (const float*)d_in[2];
    const float* b1l = (const float*)d_in[3];
    const float* w1r = (const float*)d_in[4];
    const float* w2l = (const float*)d_in[5];
    const float* b2l = (const float*)d_in[6];
    const float* w2r = (const float*)d_in[7];
    float* out = (float*)d_out;

    const int n = in_sizes[0] / F1;
    const int e = in_sizes[1] / 2;
    const int* src = ei;
    const int* dst = ei + e;

    const int l1_smem = (128 * L1_AS + F1 * L1_WS) * 4 + F1 * 4;   // ~172 KB
    const int l2_smem = (128 * L2_AS + 128 * L2_WS) * 4 + F2 * 4;  // ~100.3 KB
    cudaFuncSetAttribute(layer1_tc, cudaFuncAttributeMaxDynamicSharedMemorySize, l1_smem);
    cudaFuncSetAttribute(layer2_tc, cudaFuncAttributeMaxDynamicSharedMemorySize, l2_smem);

    // CSR build (g_deg enters zeroed; scan re-zeroes it; scatter bumps g_off)
    hist_kernel<<<(e / 4 + 255) / 256, 256>>>(dst, e);
    scan_kernel<<<1, SCAN_T>>>(n);
    scatter_kernel<<<(e / 2 + 255) / 256, 256>>>(src, dst, e);

    // layer-1 aggregation: 24 threads per dst node (lane-dense)
    agg1_kernel<<<(n + 7) / 8, 192>>>((const float4*)x, n);

    // layer 1: tf32 TC GEMM + ELU
    layer1_tc<<<(n + 127) / 128, 256, l1_smem>>>(x, w1l, b1l, w1r, n);

    // layer 2: tf32 TC GEMM (dual output)
    layer2_tc<<<(n + 127) / 128, 256, l2_smem>>>(w2l, b2l, w2r, out, n);

    // layer-2 aggregation + final combine
    long long threads = (long long)n * 16;
    agg2_kernel<<<(int)((threads + 255) / 256), 256>>>(out, n);
}

// round 15
// speedup vs baseline: 1.6024x; 1.0651x over previous
#include <cuda_runtime.h>
#include <math.h>
#include <stdint.h>

// Problem constants: N=50000, E=800000, F1=96, F2=64
#define MAXN 50000
#define MAXE 800000
#define F1 96
#define F2 64
#define SCAN_T 1024
#define SCAN_C 52              // elements per scan thread (multiple of 4)

// Scratch (device globals). __align__(16) for int4/float4 access.
__device__ __align__(16) int g_deg[MAXN];   // BSS-zero; scan re-zeroes it
__device__ __align__(16) int g_off[MAXN + 1];
__device__ int g_srcs[MAXE];
__device__ __align__(16) float g_m1[MAXN * F1];   // mean of x over neighbors
__device__ __align__(16) float g_h [MAXN * F1];   // layer-1 output
__device__ __align__(16) float g_y2[MAXN * F2];   // h @ w2_r^T

// ---------------------------------------------------------------------------
// tf32 helpers
// ---------------------------------------------------------------------------
__device__ __forceinline__ uint32_t cvt_tf32(float f) {
    uint32_t u;
    asm("cvt.rna.tf32.f32 %0, %1;" : "=r"(u) : "f"(f));
    return u;
}

__device__ __forceinline__ uint4 cvt4(float4 v) {
    return make_uint4(cvt_tf32(v.x), cvt_tf32(v.y), cvt_tf32(v.z), cvt_tf32(v.w));
}

__device__ __forceinline__ void mma_tf32(float* c,
                                         uint32_t a0, uint32_t a1,
                                         uint32_t a2, uint32_t a3,
                                         uint32_t b0, uint32_t b1) {
    asm volatile(
        "mma.sync.aligned.m16n8k8.row.col.f32.tf32.tf32.f32 "
        "{%0,%1,%2,%3}, {%4,%5,%6,%7}, {%8,%9}, {%0,%1,%2,%3};"
        : "+f"(c[0]), "+f"(c[1]), "+f"(c[2]), "+f"(c[3])
        : "r"(a0), "r"(a1), "r"(a2), "r"(a3), "r"(b0), "r"(b1));
}

__device__ __forceinline__ float elu1(float v) {
    return v > 0.f ? v : (__expf(v) - 1.0f);
}

// ---------------------------------------------------------------------------
// CSR build: histogram -> vectorized scan (clears g_deg) -> scatter
// Post-scatter convention: segment(d) = [d ? g_off[d-1] : 0, g_off[d])
// ---------------------------------------------------------------------------
__global__ void hist_kernel(const int* __restrict__ dst, int e) {
    int i4 = (blockIdx.x * blockDim.x + threadIdx.x) * 4;
    if (i4 + 3 < e) {
        int4 d = *(const int4*)(dst + i4);
        atomicAdd(&g_deg[d.x], 1);
        atomicAdd(&g_deg[d.y], 1);
        atomicAdd(&g_deg[d.z], 1);
        atomicAdd(&g_deg[d.w], 1);
    } else {
        for (int i = i4; i < e; i++) atomicAdd(&g_deg[dst[i]], 1);
    }
}

__global__ void scan_kernel(int n) {
    __shared__ int ssum[SCAN_T];
    const int t = threadIdx.x;
    const int start = t * SCAN_C;
    const int end = min(start + SCAN_C, n);

    int local = 0;
    #pragma unroll
    for (int j = 0; j < SCAN_C / 4; j++) {
        int idx = start + j * 4;
        if (idx + 3 < end) {
            int4 d = *(const int4*)(g_deg + idx);
            local += d.x + d.y + d.z + d.w;
        } else {
            for (int i = idx; i < end; i++) local += g_deg[i];
            break;
        }
    }
    ssum[t] = local;
    __syncthreads();

    for (int ofs = 1; ofs < SCAN_T; ofs <<= 1) {
        int v = (t >= ofs) ? ssum[t - ofs] : 0;
        __syncthreads();
        ssum[t] += v;
        __syncthreads();
    }
    int run = ssum[t] - local;   // exclusive prefix of this thread's chunk

    #pragma unroll
    for (int j = 0; j < SCAN_C / 4; j++) {
        int idx = start + j * 4;
        if (idx + 3 < end) {
            int4 d = *(const int4*)(g_deg + idx);
            int4 o;
            o.x = run;            run += d.x;
            o.y = run;            run += d.y;
            o.z = run;            run += d.z;
            o.w = run;            run += d.w;
            *(int4*)(g_off + idx) = o;
            *(int4*)(g_deg + idx) = make_int4(0, 0, 0, 0);
        } else {
            for (int i = idx; i < end; i++) {
                int d = g_deg[i];
                g_off[i] = run;
                run += d;
                g_deg[i] = 0;
            }
            break;
        }
    }
    if (t == SCAN_T - 1) g_off[n] = ssum[SCAN_T - 1];
}

__global__ void scatter_kernel(const int* __restrict__ src,
                               const int* __restrict__ dst, int e) {
    int i = (blockIdx.x * blockDim.x + threadIdx.x) * 2;
    if (i + 1 < e) {
        int2 s = *(const int2*)(src + i);
        int2 d = *(const int2*)(dst + i);
        int p0 = atomicAdd(&g_off[d.x], 1);
        int p1 = atomicAdd(&g_off[d.y], 1);
        g_srcs[p0] = s.x;
        g_srcs[p1] = s.y;
    } else if (i < e) {
        int p = atomicAdd(&g_off[dst[i]], 1);
        g_srcs[p] = src[i];
    }
}

// ---------------------------------------------------------------------------
// agg1: g_m1[d] = mean_{s in N(d)} x[s].
// Lane-dense: 24 threads per node, 192-thread blocks = 8 nodes/block.
// ---------------------------------------------------------------------------
__global__ void agg1_kernel(const float4* __restrict__ x4, int n) {
    int node = blockIdx.x * 8 + threadIdx.x / 24;
    int lane = threadIdx.x % 24;
    if (node >= n) return;
    int s0 = node ? g_off[node - 1] : 0;
    int s1 = g_off[node];
    float4 acc = make_float4(0.f, 0.f, 0.f, 0.f);
    int i = s0;
    for (; i + 3 < s1; i += 4) {
        int a = g_srcs[i], b = g_srcs[i+1], c = g_srcs[i+2], d = g_srcs[i+3];
        float4 va = x4[(size_t)a * 24 + lane];
        float4 vb = x4[(size_t)b * 24 + lane];
        float4 vc = x4[(size_t)c * 24 + lane];
        float4 vd = x4[(size_t)d * 24 + lane];
        acc.x += (va.x + vb.x) + (vc.x + vd.x);
        acc.y += (va.y + vb.y) + (vc.y + vd.y);
        acc.z += (va.z + vb.z) + (vc.z + vd.z);
        acc.w += (va.w + vb.w) + (vc.w + vd.w);
    }
    for (; i < s1; i++) {
        float4 va = x4[(size_t)g_srcs[i] * 24 + lane];
        acc.x += va.x; acc.y += va.y; acc.z += va.z; acc.w += va.w;
    }
    float inv = 1.0f / fmaxf((float)(s1 - s0), 1.0f);
    acc.x *= inv; acc.y *= inv; acc.z *= inv; acc.w *= inv;
    ((float4*)g_m1)[(size_t)node * 24 + lane] = acc;
}

// ---------------------------------------------------------------------------
// Layer 1 (tf32 TC GEMM + ELU), A direct-from-global:
//   h = elu([x | m1] @ [w1_l | w1_r]^T + b1)   -- M x 192 x 96
// SMEM: B[96][196] natural [n][k] only (~75.6KB) -> 2 blocks/SM.
// A fragments LDG'd per quad (contiguous 16B/row) + cvt in registers.
// ---------------------------------------------------------------------------
#define L1_WS 196
__global__ __launch_bounds__(256, 2)
void layer1_tc(const float* __restrict__ x,
               const float* __restrict__ wl,
               const float* __restrict__ bl,
               const float* __restrict__ wr,
               int n) {
    extern __shared__ uint32_t smem1[];
    uint32_t* sB = smem1;                        // [96][196] natural [n][k]
    float* sbias = (float*)(sB + F1 * L1_WS);    // [96]

    const int tid = threadIdx.x;
    const int warp = tid >> 5;
    const int lane = tid & 31;
    const int gid = lane >> 2;
    const int tig = lane & 3;
    const int base = blockIdx.x * 128;
    const int row0 = warp * 16 + gid;

    // stage B (vectorized row copy): sB[f][0..95]=wl[f], sB[f][96..191]=wr[f]
    const float4* wl4 = (const float4*)wl;
    const float4* wr4 = (const float4*)wr;
    for (int i = tid; i < F1 * 24; i += 256) {
        int f = i / 24, c = i % 24;
        *(uint4*)&sB[f * L1_WS + c * 4]      = cvt4(wl4[f * 24 + c]);
        *(uint4*)&sB[f * L1_WS + F1 + c * 4] = cvt4(wr4[f * 24 + c]);
    }
    if (tid < F1) sbias[tid] = bl[tid];
    __syncthreads();

    const int gr0 = base + row0, gr1 = gr0 + 8;
    const int rA0 = gr0 < n ? gr0 : 0;
    const int rA1 = gr1 < n ? gr1 : 0;

    float c[12][4];
    #pragma unroll
    for (int nt = 0; nt < 12; nt++)
        #pragma unroll
        for (int q = 0; q < 4; q++) c[nt][q] = 0.f;

    // K-half 1: x  (k = 0..95)
    {
        const float* p0 = x + (size_t)rA0 * F1;
        const float* p1 = x + (size_t)rA1 * F1;
        #pragma unroll 2
        for (int kb = 0; kb < 12; kb++) {
            int k0 = kb * 8;
            uint32_t a0 = cvt_tf32(p0[k0 + tig]);
            uint32_t a1 = cvt_tf32(p1[k0 + tig]);
            uint32_t a2 = cvt_tf32(p0[k0 + tig + 4]);
            uint32_t a3 = cvt_tf32(p1[k0 + tig + 4]);
            #pragma unroll
            for (int nt = 0; nt < 12; nt++) {
                uint32_t b0 = sB[(nt * 8 + gid) * L1_WS + k0 + tig];
                uint32_t b1 = sB[(nt * 8 + gid) * L1_WS + k0 + tig + 4];
                mma_tf32(c[nt], a0, a1, a2, a3, b0, b1);
            }
        }
    }
    // K-half 2: m1  (k = 96..191)
    {
        const float* p0 = g_m1 + (size_t)rA0 * F1;
        const float* p1 = g_m1 + (size_t)rA1 * F1;
        #pragma unroll 2
        for (int kb = 0; kb < 12; kb++) {
            int k0 = kb * 8;
            int kg = F1 + k0;
            uint32_t a0 = cvt_tf32(p0[k0 + tig]);
            uint32_t a1 = cvt_tf32(p1[k0 + tig]);
            uint32_t a2 = cvt_tf32(p0[k0 + tig + 4]);
            uint32_t a3 = cvt_tf32(p1[k0 + tig + 4]);
            #pragma unroll
            for (int nt = 0; nt < 12; nt++) {
                uint32_t b0 = sB[(nt * 8 + gid) * L1_WS + kg + tig];
                uint32_t b1 = sB[(nt * 8 + gid) * L1_WS + kg + tig + 4];
                mma_tf32(c[nt], a0, a1, a2, a3, b0, b1);
            }
        }
    }

    #pragma unroll
    for (int nt = 0; nt < 12; nt++) {
        int col = nt * 8 + tig * 2;
        float bi0 = sbias[col], bi1 = sbias[col + 1];
        if (gr0 < n)
            *(float2*)&g_h[(size_t)gr0 * F1 + col] =
                make_float2(elu1(c[nt][0] + bi0), elu1(c[nt][1] + bi1));
        if (gr1 < n)
            *(float2*)&g_h[(size_t)gr1 * F1 + col] =
                make_float2(elu1(c[nt][2] + bi0), elu1(c[nt][3] + bi1));
    }
}

// ---------------------------------------------------------------------------
// Layer 2 (tf32 TC GEMM, fused dual output) — R12 known-good version:
//   [out_partial | y2] = h @ [w2_l^T | w2_r^T]   -- M x 96 x 128
// SMEM: A[128][100], B[128][100] natural [n][k]; ~100.3KB -> 2 blocks/SM.
// ---------------------------------------------------------------------------
#define L2_AS 100
#define L2_WS 100
__global__ __launch_bounds__(256, 2)
void layer2_tc(const float* __restrict__ wl,
               const float* __restrict__ bl,
               const float* __restrict__ wr,
               float* __restrict__ out,
               int n) {
    extern __shared__ uint32_t smem2[];
    uint32_t* sA = smem2;                        // [128][100]
    uint32_t* sB = sA + 128 * L2_AS;             // [128][100]: rows 0..63 wl, 64..127 wr
    float* sbias = (float*)(sB + 128 * L2_WS);   // [64]

    const int tid = threadIdx.x;
    const int warp = tid >> 5;
    const int lane = tid & 31;
    const int gid = lane >> 2;
    const int tig = lane & 3;
    const int base = blockIdx.x * 128;
    const int row0 = warp * 16 + gid;

    const float4* wl4 = (const float4*)wl;
    const float4* wr4 = (const float4*)wr;
    for (int i = tid; i < 128 * 24; i += 256) {
        int nr = i / 24, c = i % 24;
        float4 v = (nr < F2) ? wl4[nr * 24 + c] : wr4[(nr - F2) * 24 + c];
        *(uint4*)&sB[nr * L2_WS + c * 4] = cvt4(v);
    }
    if (tid < F2) sbias[tid] = bl[tid];

    const float4* h4 = (const float4*)g_h;
    for (int i = tid; i < 128 * 24; i += 256) {
        int r = i / 24, c = i % 24;
        int g = base + r;
        float4 v = make_float4(0.f, 0.f, 0.f, 0.f);
        if (g < n) v = h4[(size_t)g * 24 + c];
        *(uint4*)&sA[r * L2_AS + c * 4] = cvt4(v);
    }
    __syncthreads();

    float c[16][4];
    #pragma unroll
    for (int nt = 0; nt < 16; nt++)
        #pragma unroll
        for (int q = 0; q < 4; q++) c[nt][q] = 0.f;

    #pragma unroll 2
    for (int kb = 0; kb < 12; kb++) {
        int k0 = kb * 8;
        uint32_t a0 = sA[row0 * L2_AS + k0 + tig];
        uint32_t a1 = sA[(row0 + 8) * L2_AS + k0 + tig];
        uint32_t a2 = sA[row0 * L2_AS + k0 + tig + 4];
        uint32_t a3 = sA[(row0 + 8) * L2_AS + k0 + tig + 4];
        #pragma unroll
        for (int nt = 0; nt < 16; nt++) {
            uint32_t b0 = sB[(nt * 8 + gid) * L2_WS + k0 + tig];
            uint32_t b1 = sB[(nt * 8 + gid) * L2_WS + k0 + tig + 4];
            mma_tf32(c[nt], a0, a1, a2, a3, b0, b1);
        }
    }

    int r0 = base + row0, r1 = r0 + 8;
    #pragma unroll
    for (int nt = 0; nt < 16; nt++) {
        int col = nt * 8 + tig * 2;
        if (col < F2) {
            float bi0 = sbias[col], bi1 = sbias[col + 1];
            if (r0 < n)
                *(float2*)&out[(size_t)r0 * F2 + col] =
                    make_float2(c[nt][0] + bi0, c[nt][1] + bi1);
            if (r1 < n)
                *(float2*)&out[(size_t)r1 * F2 + col] =
                    make_float2(c[nt][2] + bi0, c[nt][3] + bi1);
        } else {
            int cy = col - F2;
            if (r0 < n)
                *(float2*)&g_y2[(size_t)r0 * F2 + cy] =
                    make_float2(c[nt][0], c[nt][1]);
            if (r1 < n)
                *(float2*)&g_y2[(size_t)r1 * F2 + cy] =
                    make_float2(c[nt][2], c[nt][3]);
        }
    }
}

// ---------------------------------------------------------------------------
// agg2 + final: out[d] += mean_nbr(y2). 16 threads per dst, unroll x4.
// ---------------------------------------------------------------------------
__global__ void agg2_kernel(float* __restrict__ out, int n) {
    int tid = blockIdx.x * blockDim.x + threadIdx.x;
    int d = tid >> 4;
    int lane = tid & 15;
    if (d >= n) return;
    int s0 = d ? g_off[d - 1] : 0;
    int s1 = g_off[d];
    const float4* y4 = (const float4*)g_y2;
    float4 acc = make_float4(0.f, 0.f, 0.f, 0.f);
    int i = s0;
    for (; i + 3 < s1; i += 4) {
        int a = g_srcs[i], b = g_srcs[i+1], c = g_srcs[i+2], dd = g_srcs[i+3];
        float4 va = y4[(size_t)a * 16 + lane];
        float4 vb = y4[(size_t)b * 16 + lane];
        float4 vc = y4[(size_t)c * 16 + lane];
        float4 vd = y4[(size_t)dd * 16 + lane];
        acc.x += (va.x + vb.x) + (vc.x + vd.x);
        acc.y += (va.y + vb.y) + (vc.y + vd.y);
        acc.z += (va.z + vb.z) + (vc.z + vd.z);
        acc.w += (va.w + vb.w) + (vc.w + vd.w);
    }
    for (; i < s1; i++) {
        float4 va = y4[(size_t)g_srcs[i] * 16 + lane];
        acc.x += va.x; acc.y += va.y; acc.z += va.z; acc.w += va.w;
    }
    float inv = 1.0f / fmaxf((float)(s1 - s0), 1.0f);
    float4* o = (float4*)out + (size_t)d * 16 + lane;
    float4 ov = *o;
    ov.x += acc.x * inv; ov.y += acc.y * inv;
    ov.z += acc.z * inv; ov.w += acc.w * inv;
    *o = ov;
}

// ---------------------------------------------------------------------------
extern "C" void kernel_launch(void* const* d_in, const int* in_sizes, int n_in,
                              void* d_out, int out_size) {
    const float* x   = (const float*)d_in[0];
    const int*   ei  = (const int*)d_in[1];   // [2, E] int32
    const float* w1l = (const float*)d_in[2];
    const float* b1l = (const float*)d_in[3];
    const float* w1r = (const float*)d_in[4];
    const float* w2l = (const float*)d_in[5];
    const float* b2l = (const float*)d_in[6];
    const float* w2r = (const float*)d_in[7];
    float* out = (float*)d_out;

    const int n = in_sizes[0] / F1;
    const int e = in_sizes[1] / 2;
    const int* src = ei;
    const int* dst = ei + e;

    const int l1_smem = F1 * L1_WS * 4 + F1 * 4;                   // ~75.6 KB
    const int l2_smem = (128 * L2_AS + 128 * L2_WS) * 4 + F2 * 4;  // ~100.3 KB
    cudaFuncSetAttribute(layer1_tc, cudaFuncAttributeMaxDynamicSharedMemorySize, l1_smem);
    cudaFuncSetAttribute(layer2_tc, cudaFuncAttributeMaxDynamicSharedMemorySize, l2_smem);

    // CSR build (g_deg enters zeroed; scan re-zeroes it; scatter bumps g_off)
    hist_kernel<<<(e / 4 + 255) / 256, 256>>>(dst, e);
    scan_kernel<<<1, SCAN_T>>>(n);
    scatter_kernel<<<(e / 2 + 255) / 256, 256>>>(src, dst, e);

    // layer-1 aggregation: 24 threads per dst node (lane-dense)
    agg1_kernel<<<(n + 7) / 8, 192>>>((const float4*)x, n);

    // layer 1: tf32 TC GEMM + ELU (A direct from global)
    layer1_tc<<<(n + 127) / 128, 256, l1_smem>>>(x, w1l, b1l, w1r, n);

    // layer 2: tf32 TC GEMM (dual output, A staged in SMEM — R12 version)
    layer2_tc<<<(n + 127) / 128, 256, l2_smem>>>(w2l, b2l, w2r, out, n);

    // layer-2 aggregation + final combine
    long long threads = (long long)n * 16;
    agg2_kernel<<<(int)((threads + 255) / 256), 256>>>(out, n);
}

// round 16
// speedup vs baseline: 1.6246x; 1.0139x over previous
#include <cuda_runtime.h>
#include <math.h>
#include <stdint.h>

// Problem constants: N=50000, E=800000, F1=96, F2=64
#define MAXN 50000
#define MAXE 800000
#define F1 96
#define F2 64
#define SCAN_T 1024
#define SCAN_C 52              // elements per scan thread (multiple of 4)

// Scratch (device globals). __align__(16) for int4/float4 access.
__device__ __align__(16) int g_deg[MAXN];   // BSS-zero; scan re-zeroes it
__device__ __align__(16) int g_off[MAXN + 1];
__device__ int g_srcs[MAXE];
__device__ __align__(16) float g_m1[MAXN * F1];   // mean of x over neighbors
__device__ __align__(16) float g_h [MAXN * F1];   // layer-1 output
__device__ __align__(16) float g_y2[MAXN * F2];   // h @ w2_r^T

// ---------------------------------------------------------------------------
// tf32 helpers
// ---------------------------------------------------------------------------
__device__ __forceinline__ uint32_t cvt_tf32(float f) {
    uint32_t u;
    asm("cvt.rna.tf32.f32 %0, %1;" : "=r"(u) : "f"(f));
    return u;
}

__device__ __forceinline__ uint4 cvt4(float4 v) {
    return make_uint4(cvt_tf32(v.x), cvt_tf32(v.y), cvt_tf32(v.z), cvt_tf32(v.w));
}

__device__ __forceinline__ void mma_tf32(float* c,
                                         uint32_t a0, uint32_t a1,
                                         uint32_t a2, uint32_t a3,
                                         uint32_t b0, uint32_t b1) {
    asm volatile(
        "mma.sync.aligned.m16n8k8.row.col.f32.tf32.tf32.f32 "
        "{%0,%1,%2,%3}, {%4,%5,%6,%7}, {%8,%9}, {%0,%1,%2,%3};"
        : "+f"(c[0]), "+f"(c[1]), "+f"(c[2]), "+f"(c[3])
        : "r"(a0), "r"(a1), "r"(a2), "r"(a3), "r"(b0), "r"(b1));
}

__device__ __forceinline__ float elu1(float v) {
    return v > 0.f ? v : (__expf(v) - 1.0f);
}

// ---------------------------------------------------------------------------
// CSR build: histogram -> vectorized scan (clears g_deg) -> scatter
// Post-scatter convention: segment(d) = [d ? g_off[d-1] : 0, g_off[d])
// ---------------------------------------------------------------------------
__global__ void hist_kernel(const int* __restrict__ dst, int e) {
    int i4 = (blockIdx.x * blockDim.x + threadIdx.x) * 4;
    if (i4 + 3 < e) {
        int4 d = *(const int4*)(dst + i4);
        atomicAdd(&g_deg[d.x], 1);
        atomicAdd(&g_deg[d.y], 1);
        atomicAdd(&g_deg[d.z], 1);
        atomicAdd(&g_deg[d.w], 1);
    } else {
        for (int i = i4; i < e; i++) atomicAdd(&g_deg[dst[i]], 1);
    }
}

__global__ void scan_kernel(int n) {
    __shared__ int ssum[SCAN_T];
    const int t = threadIdx.x;
    const int start = t * SCAN_C;
    const int end = min(start + SCAN_C, n);

    int local = 0;
    #pragma unroll
    for (int j = 0; j < SCAN_C / 4; j++) {
        int idx = start + j * 4;
        if (idx + 3 < end) {
            int4 d = *(const int4*)(g_deg + idx);
            local += d.x + d.y + d.z + d.w;
        } else {
            for (int i = idx; i < end; i++) local += g_deg[i];
            break;
        }
    }
    ssum[t] = local;
    __syncthreads();

    for (int ofs = 1; ofs < SCAN_T; ofs <<= 1) {
        int v = (t >= ofs) ? ssum[t - ofs] : 0;
        __syncthreads();
        ssum[t] += v;
        __syncthreads();
    }
    int run = ssum[t] - local;   // exclusive prefix of this thread's chunk

    #pragma unroll
    for (int j = 0; j < SCAN_C / 4; j++) {
        int idx = start + j * 4;
        if (idx + 3 < end) {
            int4 d = *(const int4*)(g_deg + idx);
            int4 o;
            o.x = run;            run += d.x;
            o.y = run;            run += d.y;
            o.z = run;            run += d.z;
            o.w = run;            run += d.w;
            *(int4*)(g_off + idx) = o;
            *(int4*)(g_deg + idx) = make_int4(0, 0, 0, 0);
        } else {
            for (int i = idx; i < end; i++) {
                int d = g_deg[i];
                g_off[i] = run;
                run += d;
                g_deg[i] = 0;
            }
            break;
        }
    }
    if (t == SCAN_T - 1) g_off[n] = ssum[SCAN_T - 1];
}

__global__ void scatter_kernel(const int* __restrict__ src,
                               const int* __restrict__ dst, int e) {
    int i = (blockIdx.x * blockDim.x + threadIdx.x) * 2;
    if (i + 1 < e) {
        int2 s = *(const int2*)(src + i);
        int2 d = *(const int2*)(dst + i);
        int p0 = atomicAdd(&g_off[d.x], 1);
        int p1 = atomicAdd(&g_off[d.y], 1);
        g_srcs[p0] = s.x;
        g_srcs[p1] = s.y;
    } else if (i < e) {
        int p = atomicAdd(&g_off[dst[i]], 1);
        g_srcs[p] = src[i];
    }
}

// ---------------------------------------------------------------------------
// agg1: g_m1[d] = mean_{s in N(d)} x[s].
// Lane-dense: 24 threads per node, 192-thread blocks = 8 nodes/block.
// ---------------------------------------------------------------------------
__global__ void agg1_kernel(const float4* __restrict__ x4, int n) {
    int node = blockIdx.x * 8 + threadIdx.x / 24;
    int lane = threadIdx.x % 24;
    if (node >= n) return;
    int s0 = node ? g_off[node - 1] : 0;
    int s1 = g_off[node];
    float4 acc = make_float4(0.f, 0.f, 0.f, 0.f);
    int i = s0;
    for (; i + 3 < s1; i += 4) {
        int a = g_srcs[i], b = g_srcs[i+1], c = g_srcs[i+2], d = g_srcs[i+3];
        float4 va = x4[(size_t)a * 24 + lane];
        float4 vb = x4[(size_t)b * 24 + lane];
        float4 vc = x4[(size_t)c * 24 + lane];
        float4 vd = x4[(size_t)d * 24 + lane];
        acc.x += (va.x + vb.x) + (vc.x + vd.x);
        acc.y += (va.y + vb.y) + (vc.y + vd.y);
        acc.z += (va.z + vb.z) + (vc.z + vd.z);
        acc.w += (va.w + vb.w) + (vc.w + vd.w);
    }
    for (; i < s1; i++) {
        float4 va = x4[(size_t)g_srcs[i] * 24 + lane];
        acc.x += va.x; acc.y += va.y; acc.z += va.z; acc.w += va.w;
    }
    float inv = 1.0f / fmaxf((float)(s1 - s0), 1.0f);
    acc.x *= inv; acc.y *= inv; acc.z *= inv; acc.w *= inv;
    ((float4*)g_m1)[(size_t)node * 24 + lane] = acc;
}

// ---------------------------------------------------------------------------
// Layer 1 (tf32 TC GEMM + ELU), A direct-from-global:
//   h = elu([x | m1] @ [w1_l | w1_r]^T + b1)   -- M x 192 x 96
// SMEM: B[96][196] natural [n][k] only (~75.6KB) -> 2 blocks/SM.
// ---------------------------------------------------------------------------
#define L1_WS 196
__global__ __launch_bounds__(256, 2)
void layer1_tc(const float* __restrict__ x,
               const float* __restrict__ wl,
               const float* __restrict__ bl,
               const float* __restrict__ wr,
               int n) {
    extern __shared__ uint32_t smem1[];
    uint32_t* sB = smem1;                        // [96][196] natural [n][k]
    float* sbias = (float*)(sB + F1 * L1_WS);    // [96]

    const int tid = threadIdx.x;
    const int warp = tid >> 5;
    const int lane = tid & 31;
    const int gid = lane >> 2;
    const int tig = lane & 3;
    const int base = blockIdx.x * 128;
    const int row0 = warp * 16 + gid;

    const float4* wl4 = (const float4*)wl;
    const float4* wr4 = (const float4*)wr;
    for (int i = tid; i < F1 * 24; i += 256) {
        int f = i / 24, c = i % 24;
        *(uint4*)&sB[f * L1_WS + c * 4]      = cvt4(wl4[f * 24 + c]);
        *(uint4*)&sB[f * L1_WS + F1 + c * 4] = cvt4(wr4[f * 24 + c]);
    }
    if (tid < F1) sbias[tid] = bl[tid];
    __syncthreads();

    const int gr0 = base + row0, gr1 = gr0 + 8;
    const int rA0 = gr0 < n ? gr0 : 0;
    const int rA1 = gr1 < n ? gr1 : 0;

    float c[12][4];
    #pragma unroll
    for (int nt = 0; nt < 12; nt++)
        #pragma unroll
        for (int q = 0; q < 4; q++) c[nt][q] = 0.f;

    // K-half 1: x  (k = 0..95)
    {
        const float* p0 = x + (size_t)rA0 * F1;
        const float* p1 = x + (size_t)rA1 * F1;
        #pragma unroll 2
        for (int kb = 0; kb < 12; kb++) {
            int k0 = kb * 8;
            uint32_t a0 = cvt_tf32(p0[k0 + tig]);
            uint32_t a1 = cvt_tf32(p1[k0 + tig]);
            uint32_t a2 = cvt_tf32(p0[k0 + tig + 4]);
            uint32_t a3 = cvt_tf32(p1[k0 + tig + 4]);
            #pragma unroll
            for (int nt = 0; nt < 12; nt++) {
                uint32_t b0 = sB[(nt * 8 + gid) * L1_WS + k0 + tig];
                uint32_t b1 = sB[(nt * 8 + gid) * L1_WS + k0 + tig + 4];
                mma_tf32(c[nt], a0, a1, a2, a3, b0, b1);
            }
        }
    }
    // K-half 2: m1  (k = 96..191)
    {
        const float* p0 = g_m1 + (size_t)rA0 * F1;
        const float* p1 = g_m1 + (size_t)rA1 * F1;
        #pragma unroll 2
        for (int kb = 0; kb < 12; kb++) {
            int k0 = kb * 8;
            int kg = F1 + k0;
            uint32_t a0 = cvt_tf32(p0[k0 + tig]);
            uint32_t a1 = cvt_tf32(p1[k0 + tig]);
            uint32_t a2 = cvt_tf32(p0[k0 + tig + 4]);
            uint32_t a3 = cvt_tf32(p1[k0 + tig + 4]);
            #pragma unroll
            for (int nt = 0; nt < 12; nt++) {
                uint32_t b0 = sB[(nt * 8 + gid) * L1_WS + kg + tig];
                uint32_t b1 = sB[(nt * 8 + gid) * L1_WS + kg + tig + 4];
                mma_tf32(c[nt], a0, a1, a2, a3, b0, b1);
            }
        }
    }

    #pragma unroll
    for (int nt = 0; nt < 12; nt++) {
        int col = nt * 8 + tig * 2;
        float bi0 = sbias[col], bi1 = sbias[col + 1];
        if (gr0 < n)
            *(float2*)&g_h[(size_t)gr0 * F1 + col] =
                make_float2(elu1(c[nt][0] + bi0), elu1(c[nt][1] + bi1));
        if (gr1 < n)
            *(float2*)&g_h[(size_t)gr1 * F1 + col] =
                make_float2(elu1(c[nt][2] + bi0), elu1(c[nt][3] + bi1));
    }
}

// ---------------------------------------------------------------------------
// Layer 2 (tf32 TC GEMM, fused dual output), A direct-from-global:
//   [out_partial | y2] = h @ [w2_l^T | w2_r^T]   -- M x 96 x 128
// SMEM: B[128][100] only (~51.5KB) -> 2 blocks/SM.
// ---------------------------------------------------------------------------
#define L2_WS 100
__global__ __launch_bounds__(256, 2)
void layer2_tc(const float* __restrict__ wl,
               const float* __restrict__ bl,
               const float* __restrict__ wr,
               float* __restrict__ out,
               int n) {
    extern __shared__ uint32_t smem2[];
    uint32_t* sB = smem2;                        // [128][100]: rows 0..63 wl, 64..127 wr
    float* sbias = (float*)(sB + 128 * L2_WS);   // [64]

    const int tid = threadIdx.x;
    const int warp = tid >> 5;
    const int lane = tid & 31;
    const int gid = lane >> 2;
    const int tig = lane & 3;
    const int base = blockIdx.x * 128;
    const int row0 = warp * 16 + gid;

    const float4* wl4 = (const float4*)wl;
    const float4* wr4 = (const float4*)wr;
    for (int i = tid; i < 128 * 24; i += 256) {
        int nr = i / 24, c = i % 24;
        float4 v = (nr < F2) ? wl4[nr * 24 + c] : wr4[(nr - F2) * 24 + c];
        *(uint4*)&sB[nr * L2_WS + c * 4] = cvt4(v);
    }
    if (tid < F2) sbias[tid] = bl[tid];
    __syncthreads();

    const int gr0 = base + row0, gr1 = gr0 + 8;
    const int rA0 = gr0 < n ? gr0 : 0;
    const int rA1 = gr1 < n ? gr1 : 0;

    float c[16][4];
    #pragma unroll
    for (int nt = 0; nt < 16; nt++)
        #pragma unroll
        for (int q = 0; q < 4; q++) c[nt][q] = 0.f;

    const float* p0 = g_h + (size_t)rA0 * F1;
    const float* p1 = g_h + (size_t)rA1 * F1;
    #pragma unroll 2
    for (int kb = 0; kb < 12; kb++) {
        int k0 = kb * 8;
        uint32_t a0 = cvt_tf32(p0[k0 + tig]);
        uint32_t a1 = cvt_tf32(p1[k0 + tig]);
        uint32_t a2 = cvt_tf32(p0[k0 + tig + 4]);
        uint32_t a3 = cvt_tf32(p1[k0 + tig + 4]);
        #pragma unroll
        for (int nt = 0; nt < 16; nt++) {
            uint32_t b0 = sB[(nt * 8 + gid) * L2_WS + k0 + tig];
            uint32_t b1 = sB[(nt * 8 + gid) * L2_WS + k0 + tig + 4];
            mma_tf32(c[nt], a0, a1, a2, a3, b0, b1);
        }
    }

    #pragma unroll
    for (int nt = 0; nt < 16; nt++) {
        int col = nt * 8 + tig * 2;
        if (col < F2) {
            float bi0 = sbias[col], bi1 = sbias[col + 1];
            if (gr0 < n)
                *(float2*)&out[(size_t)gr0 * F2 + col] =
                    make_float2(c[nt][0] + bi0, c[nt][1] + bi1);
            if (gr1 < n)
                *(float2*)&out[(size_t)gr1 * F2 + col] =
                    make_float2(c[nt][2] + bi0, c[nt][3] + bi1);
        } else {
            int cy = col - F2;
            if (gr0 < n)
                *(float2*)&g_y2[(size_t)gr0 * F2 + cy] =
                    make_float2(c[nt][0], c[nt][1]);
            if (gr1 < n)
                *(float2*)&g_y2[(size_t)gr1 * F2 + cy] =
                    make_float2(c[nt][2], c[nt][3]);
        }
    }
}

// ---------------------------------------------------------------------------
// agg2 + final: out[d] += mean_nbr(y2). 16 threads per dst, unroll x4.
// ---------------------------------------------------------------------------
__global__ void agg2_kernel(float* __restrict__ out, int n) {
    int tid = blockIdx.x * blockDim.x + threadIdx.x;
    int d = tid >> 4;
    int lane = tid & 15;
    if (d >= n) return;
    int s0 = d ? g_off[d - 1] : 0;
    int s1 = g_off[d];
    const float4* y4 = (const float4*)g_y2;
    float4 acc = make_float4(0.f, 0.f, 0.f, 0.f);
    int i = s0;
    for (; i + 3 < s1; i += 4) {
        int a = g_srcs[i], b = g_srcs[i+1], c = g_srcs[i+2], dd = g_srcs[i+3];
        float4 va = y4[(size_t)a * 16 + lane];
        float4 vb = y4[(size_t)b * 16 + lane];
        float4 vc = y4[(size_t)c * 16 + lane];
        float4 vd = y4[(size_t)dd * 16 + lane];
        acc.x += (va.x + vb.x) + (vc.x + vd.x);
        acc.y += (va.y + vb.y) + (vc.y + vd.y);
        acc.z += (va.z + vb.z) + (vc.z + vd.z);
        acc.w += (va.w + vb.w) + (vc.w + vd.w);
    }
    for (; i < s1; i++) {
        float4 va = y4[(size_t)g_srcs[i] * 16 + lane];
        acc.x += va.x; acc.y += va.y; acc.z += va.z; acc.w += va.w;
    }
    float inv = 1.0f / fmaxf((float)(s1 - s0), 1.0f);
    float4* o = (float4*)out + (size_t)d * 16 + lane;
    float4 ov = *o;
    ov.x += acc.x * inv; ov.y += acc.y * inv;
    ov.z += acc.z * inv; ov.w += acc.w * inv;
    *o = ov;
}

// ---------------------------------------------------------------------------
extern "C" void kernel_launch(void* const* d_in, const int* in_sizes, int n_in,
                              void* d_out, int out_size) {
    const float* x   = (const float*)d_in[0];
    const int*   ei  = (const int*)d_in[1];   // [2, E] int32
    const float* w1l = (const float*)d_in[2];
    const float* b1l = (const float*)d_in[3];
    const float* w1r = (const float*)d_in[4];
    const float* w2l = (const float*)d_in[5];
    const float* b2l = (const float*)d_in[6];
    const float* w2r = (const float*)d_in[7];
    float* out = (float*)d_out;

    const int n = in_sizes[0] / F1;
    const int e = in_sizes[1] / 2;
    const int* src = ei;
    const int* dst = ei + e;

    const int l1_smem = F1 * L1_WS * 4 + F1 * 4;     // ~75.6 KB
    const int l2_smem = 128 * L2_WS * 4 + F2 * 4;    // ~51.5 KB
    cudaFuncSetAttribute(layer1_tc, cudaFuncAttributeMaxDynamicSharedMemorySize, l1_smem);
    cudaFuncSetAttribute(layer2_tc, cudaFuncAttributeMaxDynamicSharedMemorySize, l2_smem);

    // CSR build (g_deg enters zeroed; scan re-zeroes it; scatter bumps g_off)
    hist_kernel<<<(e / 4 + 255) / 256, 256>>>(dst, e);
    scan_kernel<<<1, SCAN_T>>>(n);
    scatter_kernel<<<(e / 2 + 255) / 256, 256>>>(src, dst, e);

    // layer-1 aggregation: 24 threads per dst node (lane-dense)
    agg1_kernel<<<(n + 7) / 8, 192>>>((const float4*)x, n);

    // layer 1: tf32 TC GEMM + ELU (A direct from global)
    layer1_tc<<<(n + 127) / 128, 256, l1_smem>>>(x, w1l, b1l, w1r, n);

    // layer 2: tf32 TC GEMM (dual output, A direct from global)
    layer2_tc<<<(n + 127) / 128, 256, l2_smem>>>(w2l, b2l, w2r, out, n);

    // layer-2 aggregation + final combine
    long long threads = (long long)n * 16;
    agg2_kernel<<<(int)((threads + 255) / 256), 256>>>(out, n);
}